// round 9
// baseline (speedup 1.0000x reference)
#include <cuda_runtime.h>
#include <math.h>

#define HDIM 1024
#define LDIM 512
#define VDIM 50257
#define NB   592
#define NT   256

// dynamic smem: [0,8192) staging sbuf | phase5: [0,4096) h_new, [4096,53248) 3x16KB tiles
#define DSMEM 53248

// ---------------- device scratch (no allocations allowed) ----------------
__device__ float g_attn[LDIM];
__device__ float g_wctx[HDIM];
__device__ float g_vout[HDIM];
__device__ float g_gh[3 * HDIM];
__device__ float g_hnew[HDIM];
__device__ float g_logits[VDIM];
__device__ float g_expsum;
__device__ unsigned g_bar_cnt = 0;
__device__ volatile unsigned g_bar_gen = 0;

__device__ __forceinline__ void grid_barrier() {
    __syncthreads();
    if (threadIdx.x == 0) {
        unsigned gen = g_bar_gen;
        __threadfence();
        unsigned t = atomicAdd(&g_bar_cnt, 1u);
        if (t == NB - 1) {
            g_bar_cnt = 0;
            __threadfence();
            g_bar_gen = gen + 1;
        } else {
            while (g_bar_gen == gen) __nanosleep(64);
        }
        __threadfence();
    }
    __syncthreads();
}

__device__ __forceinline__ float warpReduce(float v) {
    #pragma unroll
    for (int o = 16; o; o >>= 1) v += __shfl_down_sync(0xffffffffu, v, o);
    return v;
}

__global__ void __launch_bounds__(NT, 4)
fused_decoder(const int* __restrict__ x, const float* __restrict__ hidden,
              const float* __restrict__ enc, const float* __restrict__ emb,
              const float* __restrict__ Ww, const float* __restrict__ bw,
              const float* __restrict__ Wc, const float* __restrict__ bc,
              const float* __restrict__ Wih, const float* __restrict__ Whh,
              const float* __restrict__ bih, const float* __restrict__ bhh,
              const float* __restrict__ Wo, const float* __restrict__ bo,
              float* __restrict__ out) {
    extern __shared__ char dsmem[];
    float* sbuf = (float*)dsmem;             // 2048 floats (prefix staging)
    float4* sb4 = (float4*)dsmem;
    __shared__ float sred[256];
    __shared__ float swarp[8];
    __shared__ float spart[8];
    __shared__ float s_m, s_inv, s_esum;

    const int blk = blockIdx.x, t = threadIdx.x;
    const int warp = t >> 5, lane = t & 31;

    // ================= Phase 1: attn logits + gh = Whh@h + bhh ============
    if (blk < 64) {
        const float4* e4 = (const float4*)(emb + (size_t)x[0] * HDIM);
        const float4* h4 = (const float4*)hidden;
        sb4[t] = e4[t];
        sb4[256 + t] = h4[t];
        __syncthreads();
        int row = blk * 8 + warp;
        const float4* w4 = (const float4*)Ww + (size_t)row * 512;
        float acc = 0.f;
        #pragma unroll
        for (int k = 0; k < 16; k++) {
            int idx = k * 32 + lane;
            float4 a = w4[idx], b = sb4[idx];
            acc += a.x * b.x + a.y * b.y + a.z * b.z + a.w * b.w;
        }
        acc = warpReduce(acc);
        if (lane == 0) g_attn[row] = acc + bw[row];
    } else {
        if (blk == 64) {
            g_wctx[t] = 0.f; g_wctx[t + 256] = 0.f;
            g_wctx[t + 512] = 0.f; g_wctx[t + 768] = 0.f;
            if (t == 0) g_expsum = 0.f;
        }
        const float4* h4 = (const float4*)hidden;
        sb4[t] = h4[t];
        __syncthreads();
        int gw = (blk - 64) * 8 + warp;
        for (int r = gw; r < 3 * HDIM; r += (NB - 64) * 8) {
            const float4* w4 = (const float4*)Whh + (size_t)r * 256;
            float acc = 0.f;
            #pragma unroll
            for (int k = 0; k < 8; k++) {
                int idx = k * 32 + lane;
                float4 a = w4[idx], b = sb4[idx];
                acc += a.x * b.x + a.y * b.y + a.z * b.z + a.w * b.w;
            }
            acc = warpReduce(acc);
            if (lane == 0) g_gh[r] = acc + bhh[r];
        }
    }
    grid_barrier();

    // ================= Phase 2: softmax (redundant per block) + wctx ======
    if (blk < 128) {
        sbuf[t] = __ldcg(g_attn + t);
        sbuf[t + 256] = __ldcg(g_attn + t + 256);
        __syncthreads();
        sred[t] = fmaxf(sbuf[t], sbuf[t + 256]);
        __syncthreads();
        #pragma unroll
        for (int o = 128; o; o >>= 1) { if (t < o) sred[t] = fmaxf(sred[t], sred[t + o]); __syncthreads(); }
        if (t == 0) s_m = sred[0];
        __syncthreads();
        float m = s_m;
        sred[t] = expf(sbuf[t] - m) + expf(sbuf[t + 256] - m);
        __syncthreads();
        #pragma unroll
        for (int o = 128; o; o >>= 1) { if (t < o) sred[t] += sred[t + o]; __syncthreads(); }
        if (t == 0) s_inv = 1.f / sred[0];
        __syncthreads();
        float inv = s_inv;

        int c = blk & 3, lch = blk >> 2;
        int l0 = lch * 16;
        int col = c * 256 + t;
        float acc = 0.f;
        #pragma unroll
        for (int j = 0; j < 16; j++) {
            float w = expf(sbuf[l0 + j] - m);
            acc += w * enc[(size_t)(l0 + j) * HDIM + col];
        }
        atomicAdd(&g_wctx[col], acc * inv);

        if (blk == 0) {
            out[VDIM + HDIM + t] = expf(sbuf[t] - m) * inv;
            out[VDIM + HDIM + t + 256] = expf(sbuf[t + 256] - m) * inv;
        }
    }
    grid_barrier();

    // ================= Phase 3: vout = relu(Wc @ [emb, wctx] + bc) ========
    {
        const float4* e4 = (const float4*)(emb + (size_t)x[0] * HDIM);
        sb4[t] = e4[t];
        sb4[256 + t] = __ldcg((const float4*)g_wctx + t);
        __syncthreads();
        if (blk < 128) {
            int row = blk * 8 + warp;
            const float4* w4 = (const float4*)Wc + (size_t)row * 512;
            float acc = 0.f;
            #pragma unroll
            for (int k = 0; k < 16; k++) {
                int idx = k * 32 + lane;
                float4 a = w4[idx], b = sb4[idx];
                acc += a.x * b.x + a.y * b.y + a.z * b.z + a.w * b.w;
            }
            acc = warpReduce(acc);
            if (lane == 0) g_vout[row] = fmaxf(acc + bc[row], 0.f);
        }
    }
    grid_barrier();

    // ================= Phase 4: GRU gates + h_new (warp per output) =======
    {
        sb4[t] = __ldcg((const float4*)g_vout + t);
        __syncthreads();
        if (blk < 128) {
            int i = blk * 8 + warp;
            const float4* wr = (const float4*)Wih + (size_t)i * 256;
            const float4* wz = (const float4*)Wih + (size_t)(i + HDIM) * 256;
            const float4* wn = (const float4*)Wih + (size_t)(i + 2 * HDIM) * 256;
            float a0 = 0.f, a1 = 0.f, a2 = 0.f;
            #pragma unroll
            for (int k = 0; k < 8; k++) {
                int idx = k * 32 + lane;
                float4 b = sb4[idx];
                float4 m0 = wr[idx]; a0 += m0.x * b.x + m0.y * b.y + m0.z * b.z + m0.w * b.w;
                float4 m1 = wz[idx]; a1 += m1.x * b.x + m1.y * b.y + m1.z * b.z + m1.w * b.w;
                float4 m2 = wn[idx]; a2 += m2.x * b.x + m2.y * b.y + m2.z * b.z + m2.w * b.w;
            }
            a0 = warpReduce(a0); a1 = warpReduce(a1); a2 = warpReduce(a2);
            if (lane == 0) {
                float gh_r = __ldcg(&g_gh[i]);
                float gh_z = __ldcg(&g_gh[i + HDIM]);
                float gh_n = __ldcg(&g_gh[i + 2 * HDIM]);
                float gi_r = a0 + bih[i];
                float gi_z = a1 + bih[i + HDIM];
                float gi_n = a2 + bih[i + 2 * HDIM];
                float r = 1.f / (1.f + expf(-(gi_r + gh_r)));
                float z = 1.f / (1.f + expf(-(gi_z + gh_z)));
                float n = tanhf(gi_n + r * gh_n);
                float hn = (1.f - z) * n + z * hidden[i];
                g_hnew[i] = hn;
                out[VDIM + i] = hn;
            }
        }
    }
    grid_barrier();

    // ====== Phase 5: vocab GEMV via cp.async tile pipeline =================
    {
        float4* hh = (float4*)dsmem;                    // [256] h_new
        float4* tiles = (float4*)(dsmem + 4096);        // 3 bufs x 1024 float4
        hh[t] = ((const float4*)g_hnew)[t];
        if (t == 0) s_esum = 0.f;

        int start = (int)(((long)blk * VDIM) / NB);
        int end   = (int)(((long)(blk + 1) * VDIM) / NB);
        int nrows = end - start;                        // ~85
        int ntiles = (nrows + 3) >> 2;
        const char* wbase = (const char*)(Wo + (size_t)start * HDIM);

        // prologue: issue tiles 0,1,2
        #pragma unroll
        for (int p = 0; p < 3; p++) {
            int nvalid = min(4, nrows - p * 4) * 256;   // float4 count (may be <=0)
            char* dst = (char*)(tiles + (p % 3) * 1024);
            const char* src = wbase + (size_t)p * 4 * HDIM * 4;
            #pragma unroll
            for (int j = 0; j < 4; j++) {
                int idx = t + j * 256;
                if (idx < nvalid) {
                    unsigned saddr = (unsigned)__cvta_generic_to_shared(dst + idx * 16);
                    asm volatile("cp.async.cg.shared.global [%0], [%1], 16;\n"
                                 :: "r"(saddr), "l"(src + (size_t)idx * 16));
                }
            }
            asm volatile("cp.async.commit_group;\n");
        }

        int rt = warp >> 1;        // row in tile 0..3
        int half = warp & 1;       // which 512-half
        for (int i = 0; i < ntiles; i++) {
            asm volatile("cp.async.wait_group 2;\n" ::: "memory");
            __syncthreads();
            // compute tile i from buf i%3: 2 warps per row
            int buf = i % 3;
            int row = i * 4 + rt;
            float acc = 0.f;
            if (row < nrows) {
                const float4* wrow = tiles + buf * 1024 + rt * 256 + half * 128;
                const float4* hrow = hh + half * 128;
                #pragma unroll
                for (int k = 0; k < 4; k++) {
                    float4 a = wrow[k * 32 + lane];
                    float4 b = hrow[k * 32 + lane];
                    acc += a.x * b.x + a.y * b.y + a.z * b.z + a.w * b.w;
                }
            }
            acc = warpReduce(acc);
            if (lane == 0) spart[warp] = acc;
            __syncthreads();
            if (t < 4 && i * 4 + t < nrows) {
                int r = start + i * 4 + t;
                float lg = spart[2 * t] + spart[2 * t + 1] + bo[r];
                g_logits[r] = lg;
                atomicAdd(&s_esum, expf(lg));
            }
            // issue tile i+3 into the buffer just consumed
            {
                int p = i + 3;
                int nvalid = min(4, nrows - p * 4) * 256;
                char* dst = (char*)(tiles + buf * 1024);
                const char* src = wbase + (size_t)p * 4 * HDIM * 4;
                #pragma unroll
                for (int j = 0; j < 4; j++) {
                    int idx = t + j * 256;
                    if (idx < nvalid) {
                        unsigned saddr = (unsigned)__cvta_generic_to_shared(dst + idx * 16);
                        asm volatile("cp.async.cg.shared.global [%0], [%1], 16;\n"
                                     :: "r"(saddr), "l"(src + (size_t)idx * 16));
                    }
                }
                asm volatile("cp.async.commit_group;\n");
            }
        }
        __syncthreads();
        if (t == 0) atomicAdd(&g_expsum, s_esum);
    }
    grid_barrier();

    // ================= Phase 6: log_softmax write ==========================
    {
        float lse = logf(__ldcg(&g_expsum));
        for (int v = blk * NT + t; v < VDIM; v += NB * NT)
            out[v] = __ldcg(&g_logits[v]) - lse;
    }
}

// ---------------------------------------------------------------------------
extern "C" void kernel_launch(void* const* d_in, const int* in_sizes, int n_in,
                              void* d_out, int out_size) {
    const int*   x      = (const int*)  d_in[0];
    const float* hidden = (const float*)d_in[1];
    const float* enc    = (const float*)d_in[2];
    const float* emb    = (const float*)d_in[3];
    const float* Ww     = (const float*)d_in[4];
    const float* bw     = (const float*)d_in[5];
    const float* Wc     = (const float*)d_in[6];
    const float* bc     = (const float*)d_in[7];
    const float* Wih    = (const float*)d_in[8];
    const float* Whh    = (const float*)d_in[9];
    const float* bih    = (const float*)d_in[10];
    const float* bhh    = (const float*)d_in[11];
    const float* Wo     = (const float*)d_in[12];
    const float* bo     = (const float*)d_in[13];
    float* out = (float*)d_out;

    static int smem_set = 0;
    if (!smem_set) {
        cudaFuncSetAttribute(fused_decoder,
                             cudaFuncAttributeMaxDynamicSharedMemorySize, DSMEM);
        smem_set = 1;
    }
    fused_decoder<<<NB, NT, DSMEM>>>(x, hidden, enc, emb, Ww, bw, Wc, bc,
                                     Wih, Whh, bih, bhh, Wo, bo, out);
}

// round 11
// speedup vs baseline: 1.2089x; 1.2089x over previous
#include <cuda_runtime.h>
#include <math.h>

#define HDIM 1024
#define LDIM 512
#define VDIM 50257
#define NB   592
#define NT   256
#define NWARPS (NB * 8)

// ---------------- device scratch (no allocations allowed) ----------------
__device__ float g_attn[LDIM];
__device__ float g_wctx[HDIM];
__device__ float g_vemb[HDIM];     // Wc[:, :1024] @ emb  (computed in phase 1)
__device__ float g_vout[HDIM];
__device__ float g_gh[3 * HDIM];
__device__ float g_hnew[HDIM];
__device__ float g_logits[VDIM];
__device__ float g_expsum;
__device__ unsigned g_bar_cnt = 0;
__device__ volatile unsigned g_bar_gen = 0;

__device__ __forceinline__ void grid_barrier() {
    __syncthreads();
    if (threadIdx.x == 0) {
        unsigned gen = g_bar_gen;
        __threadfence();
        unsigned t = atomicAdd(&g_bar_cnt, 1u);
        if (t == NB - 1) {
            g_bar_cnt = 0;
            __threadfence();
            g_bar_gen = gen + 1;
        } else {
            while (g_bar_gen == gen) __nanosleep(64);
        }
        __threadfence();
    }
    __syncthreads();
}

__device__ __forceinline__ float warpReduce(float v) {
    #pragma unroll
    for (int o = 16; o; o >>= 1) v += __shfl_down_sync(0xffffffffu, v, o);
    return v;
}

__global__ void __launch_bounds__(NT, 4)
fused_decoder(const int* __restrict__ x, const float* __restrict__ hidden,
              const float* __restrict__ enc, const float* __restrict__ emb,
              const float* __restrict__ Ww, const float* __restrict__ bw,
              const float* __restrict__ Wc, const float* __restrict__ bc,
              const float* __restrict__ Wih, const float* __restrict__ Whh,
              const float* __restrict__ bih, const float* __restrict__ bhh,
              const float* __restrict__ Wo, const float* __restrict__ bo,
              float* __restrict__ out) {
    __shared__ float sbuf[2048];
    __shared__ float sred[256];
    __shared__ float swarp[8];
    __shared__ float sg[8][3];
    __shared__ float s_m, s_inv;

    const int blk = blockIdx.x, t = threadIdx.x;
    const int warp = t >> 5, lane = t & 31;
    float4* sb4 = (float4*)sbuf;

    // ============ Phase 1: attn | gh = Whh@h | vemb = Wc_left@emb =========
    {
        const float4* e4 = (const float4*)(emb + (size_t)x[0] * HDIM);
        const float4* h4 = (const float4*)hidden;
        sb4[t] = e4[t];
        sb4[256 + t] = h4[t];
        if (blk == 64) {
            g_wctx[t] = 0.f; g_wctx[t + 256] = 0.f;
            g_wctx[t + 512] = 0.f; g_wctx[t + 768] = 0.f;
            if (t == 0) g_expsum = 0.f;
        }
        __syncthreads();
        int j = blk * 8 + warp;                  // 0..4735
        if (j < 512) {
            // attention row: 2048-dot against [emb, hidden]
            const float4* w4 = (const float4*)Ww + (size_t)j * 512;
            float acc = 0.f;
            #pragma unroll
            for (int k = 0; k < 16; k++) {
                int idx = k * 32 + lane;
                float4 a = w4[idx], b = sb4[idx];
                acc += a.x * b.x + a.y * b.y + a.z * b.z + a.w * b.w;
            }
            acc = warpReduce(acc);
            if (lane == 0) g_attn[j] = acc + bw[j];
        } else if (j < 3584) {
            // gh row: 1024-dot against hidden
            int r = j - 512;
            const float4* w4 = (const float4*)Whh + (size_t)r * 256;
            float acc = 0.f;
            #pragma unroll
            for (int k = 0; k < 8; k++) {
                int idx = k * 32 + lane;
                float4 a = w4[idx], b = sb4[256 + idx];
                acc += a.x * b.x + a.y * b.y + a.z * b.z + a.w * b.w;
            }
            acc = warpReduce(acc);
            if (lane == 0) g_gh[r] = acc + bhh[r];
        } else if (j < 4608) {
            // vemb row: Wc row first half (emb), 1024-dot
            int r = j - 3584;
            const float4* w4 = (const float4*)Wc + (size_t)r * 512;
            float acc = 0.f;
            #pragma unroll
            for (int k = 0; k < 8; k++) {
                int idx = k * 32 + lane;
                float4 a = w4[idx], b = sb4[idx];   // emb half
                acc += a.x * b.x + a.y * b.y + a.z * b.z + a.w * b.w;
            }
            acc = warpReduce(acc);
            if (lane == 0) g_vemb[r] = acc;
        }
    }
    grid_barrier();

    // ================= Phase 2: softmax (redundant per block) + wctx ======
    if (blk < 128) {
        sbuf[t] = __ldcg(g_attn + t);
        sbuf[t + 256] = __ldcg(g_attn + t + 256);
        __syncthreads();
        sred[t] = fmaxf(sbuf[t], sbuf[t + 256]);
        __syncthreads();
        #pragma unroll
        for (int o = 128; o; o >>= 1) { if (t < o) sred[t] = fmaxf(sred[t], sred[t + o]); __syncthreads(); }
        if (t == 0) s_m = sred[0];
        __syncthreads();
        float m = s_m;
        sred[t] = expf(sbuf[t] - m) + expf(sbuf[t + 256] - m);
        __syncthreads();
        #pragma unroll
        for (int o = 128; o; o >>= 1) { if (t < o) sred[t] += sred[t + o]; __syncthreads(); }
        if (t == 0) s_inv = 1.f / sred[0];
        __syncthreads();
        float inv = s_inv;

        int c = blk & 3, lch = blk >> 2;         // 4 col-chunks x 32 L-chunks
        int l0 = lch * 16;
        int col = c * 256 + t;
        float acc = 0.f;
        #pragma unroll
        for (int j = 0; j < 16; j++) {
            float w = expf(sbuf[l0 + j] - m);
            acc += w * enc[(size_t)(l0 + j) * HDIM + col];
        }
        atomicAdd(&g_wctx[col], acc * inv);

        if (blk == 0) {   // weights output
            out[VDIM + HDIM + t] = expf(sbuf[t] - m) * inv;
            out[VDIM + HDIM + t + 256] = expf(sbuf[t + 256] - m) * inv;
        }
    }
    grid_barrier();

    // ========= Phase 3: vout = relu(vemb + Wc_right@wctx + bc) ============
    {
        sb4[256 + t] = __ldcg((const float4*)g_wctx + t);
        __syncthreads();
        if (blk < 128) {
            int row = blk * 8 + warp;
            const float4* w4 = (const float4*)Wc + (size_t)row * 512 + 256;  // wctx half
            float acc = 0.f;
            #pragma unroll
            for (int k = 0; k < 8; k++) {                 // FIXED: full 256 float4
                int idx = k * 32 + lane;
                float4 a = w4[idx], b = sb4[256 + idx];
                acc += a.x * b.x + a.y * b.y + a.z * b.z + a.w * b.w;
            }
            acc = warpReduce(acc);
            if (lane == 0)
                g_vout[row] = fmaxf(acc + __ldcg(&g_vemb[row]) + bc[row], 0.f);
        }
    }
    grid_barrier();

    // ===== Phase 4: GRU gates (256 blocks, 2 warps/row over halves) =======
    {
        sb4[t] = __ldcg((const float4*)g_vout + t);
        __syncthreads();
        if (blk < 256) {
            int i = blk * 4 + (warp >> 1);       // 0..1023
            int half = warp & 1;                 // 512-float half
            const float4* wr = (const float4*)Wih + (size_t)i * 256 + half * 128;
            const float4* wz = (const float4*)Wih + (size_t)(i + HDIM) * 256 + half * 128;
            const float4* wn = (const float4*)Wih + (size_t)(i + 2 * HDIM) * 256 + half * 128;
            const float4* vb = sb4 + half * 128;
            float a0 = 0.f, a1 = 0.f, a2 = 0.f;
            #pragma unroll
            for (int k = 0; k < 4; k++) {
                int idx = k * 32 + lane;
                float4 b = vb[idx];
                float4 m0 = wr[idx]; a0 += m0.x * b.x + m0.y * b.y + m0.z * b.z + m0.w * b.w;
                float4 m1 = wz[idx]; a1 += m1.x * b.x + m1.y * b.y + m1.z * b.z + m1.w * b.w;
                float4 m2 = wn[idx]; a2 += m2.x * b.x + m2.y * b.y + m2.z * b.z + m2.w * b.w;
            }
            a0 = warpReduce(a0); a1 = warpReduce(a1); a2 = warpReduce(a2);
            if (lane == 0) { sg[warp][0] = a0; sg[warp][1] = a1; sg[warp][2] = a2; }
            __syncthreads();
            if (t < 4) {
                int i2 = blk * 4 + t;
                float gi_r = sg[2 * t][0] + sg[2 * t + 1][0] + bih[i2];
                float gi_z = sg[2 * t][1] + sg[2 * t + 1][1] + bih[i2 + HDIM];
                float gi_n = sg[2 * t][2] + sg[2 * t + 1][2] + bih[i2 + 2 * HDIM];
                float gh_r = __ldcg(&g_gh[i2]);
                float gh_z = __ldcg(&g_gh[i2 + HDIM]);
                float gh_n = __ldcg(&g_gh[i2 + 2 * HDIM]);
                float r = 1.f / (1.f + expf(-(gi_r + gh_r)));
                float z = 1.f / (1.f + expf(-(gi_z + gh_z)));
                float n = tanhf(gi_n + r * gh_n);
                float hn = (1.f - z) * n + z * hidden[i2];
                g_hnew[i2] = hn;
                out[VDIM + i2] = hn;
            }
        }
    }
    grid_barrier();

    // ====== Phase 5: vocab GEMV + exp-sum (champion R4 structure) ==========
    {
        sb4[t] = __ldcg((const float4*)g_hnew + t);
        __syncthreads();
        int gw = blk * 8 + warp;
        float esum = 0.f;
        for (int r = gw; r < VDIM; r += 2 * NWARPS) {
            int rB = r + NWARPS;
            bool vB = rB < VDIM;
            const float4* wA = (const float4*)Wo + (size_t)r * 256;
            const float4* wB = (const float4*)Wo + (size_t)rB * 256;
            float accA = 0.f, accB = 0.f;
            #pragma unroll
            for (int k = 0; k < 8; k++) {
                int idx = k * 32 + lane;
                float4 b = sb4[idx];
                float4 a = wA[idx];
                accA += a.x * b.x + a.y * b.y + a.z * b.z + a.w * b.w;
                if (vB) {
                    float4 a2 = wB[idx];
                    accB += a2.x * b.x + a2.y * b.y + a2.z * b.z + a2.w * b.w;
                }
            }
            accA = warpReduce(accA);
            accB = warpReduce(accB);
            if (lane == 0) {
                float lA = accA + bo[r];
                g_logits[r] = lA;
                esum += expf(lA);
                if (vB) {
                    float lB = accB + bo[rB];
                    g_logits[rB] = lB;
                    esum += expf(lB);
                }
            }
        }
        if (lane == 0) swarp[warp] = esum;
        __syncthreads();
        if (t == 0) {
            float s = 0.f;
            #pragma unroll
            for (int w = 0; w < 8; w++) s += swarp[w];
            atomicAdd(&g_expsum, s);
        }
    }
    grid_barrier();

    // ================= Phase 6: log_softmax write ==========================
    {
        float lse = logf(__ldcg(&g_expsum));
        for (int v = blk * NT + t; v < VDIM; v += NB * NT)
            out[v] = __ldcg(&g_logits[v]) - lse;
    }
}

// ---------------------------------------------------------------------------
extern "C" void kernel_launch(void* const* d_in, const int* in_sizes, int n_in,
                              void* d_out, int out_size) {
    const int*   x      = (const int*)  d_in[0];
    const float* hidden = (const float*)d_in[1];
    const float* enc    = (const float*)d_in[2];
    const float* emb    = (const float*)d_in[3];
    const float* Ww     = (const float*)d_in[4];
    const float* bw     = (const float*)d_in[5];
    const float* Wc     = (const float*)d_in[6];
    const float* bc     = (const float*)d_in[7];
    const float* Wih    = (const float*)d_in[8];
    const float* Whh    = (const float*)d_in[9];
    const float* bih    = (const float*)d_in[10];
    const float* bhh    = (const float*)d_in[11];
    const float* Wo     = (const float*)d_in[12];
    const float* bo     = (const float*)d_in[13];
    float* out = (float*)d_out;

    fused_decoder<<<NB, NT>>>(x, hidden, enc, emb, Ww, bw, Wc, bc,
                              Wih, Whh, bih, bhh, Wo, bo, out);
}